// round 1
// baseline (speedup 1.0000x reference)
#include <cuda_runtime.h>
#include <cuda_bf16.h>

#define N_NODES 50000
#define N_EDGES 800000

// -------- scratch (static device allocations; no cudaMalloc allowed) --------
__device__ float g_h1[N_NODES * 64];     // GEMM output / agg input
__device__ float g_h2[N_NODES * 64];     // agg output / GEMM input
__device__ float g_hid[N_NODES * 100];   // dense hidden
__device__ int   g_deg[N_NODES];
__device__ int   g_rowptr[N_NODES + 1];
__device__ int   g_cursor[N_NODES];
__device__ int   g_src[N_EDGES];
__device__ float g_w[N_EDGES];

// ---------------------------- CSR construction -----------------------------
__global__ void zero_deg_kernel() {
    int i = blockIdx.x * blockDim.x + threadIdx.x;
    if (i < N_NODES) g_deg[i] = 0;
}

__global__ void hist_kernel(const int* __restrict__ dst) {
    int i = blockIdx.x * blockDim.x + threadIdx.x;
    if (i < N_EDGES) atomicAdd(&g_deg[dst[i]], 1);
}

// single block, 1024 threads: exclusive scan of degrees -> rowptr, cursor
__global__ void scan_kernel() {
    __shared__ int sh[1024];
    const int T = 1024;
    int t = threadIdx.x;
    const int per = (N_NODES + T - 1) / T;
    int s = t * per;
    int e = s + per; if (e > N_NODES) e = N_NODES;
    int sum = 0;
    for (int i = s; i < e; i++) sum += g_deg[i];
    sh[t] = sum;
    __syncthreads();
    for (int off = 1; off < T; off <<= 1) {
        int v = (t >= off) ? sh[t - off] : 0;
        __syncthreads();
        sh[t] += v;
        __syncthreads();
    }
    int run = (t == 0) ? 0 : sh[t - 1];
    for (int i = s; i < e; i++) {
        g_rowptr[i] = run;
        g_cursor[i] = run;
        run += g_deg[i];
    }
    if (t == T - 1) g_rowptr[N_NODES] = sh[T - 1];
}

__global__ void scatter_kernel(const int* __restrict__ src,
                               const int* __restrict__ dst,
                               const float* __restrict__ w) {
    int i = blockIdx.x * blockDim.x + threadIdx.x;
    if (i >= N_EDGES) return;
    int d = dst[i];
    int pos = atomicAdd(&g_cursor[d], 1);
    g_src[pos] = src[i];
    g_w[pos]   = w[i];
}

// ------------------------------- small GEMM ---------------------------------
// out[row, :F] = A[row, :64] @ W[64, F]  (+bias, swish if SWISH)
// blockDim.x = F/4 col-groups, blockDim.y = rows per block
template<int F, bool SWISH>
__global__ void gemm_kernel(const float* __restrict__ A,
                            const float* __restrict__ W,
                            const float* __restrict__ bias,
                            float* __restrict__ out) {
    __shared__ float Ws[64 * F];
    int nth = blockDim.x * blockDim.y;
    int tid = threadIdx.y * blockDim.x + threadIdx.x;
    for (int i = tid; i < 64 * F; i += nth) Ws[i] = W[i];
    __syncthreads();

    int row = blockIdx.x * blockDim.y + threadIdx.y;
    if (row >= N_NODES) return;
    int cg = threadIdx.x;

    float4 acc = make_float4(0.f, 0.f, 0.f, 0.f);
    const float* a = A + row * 64;
#pragma unroll
    for (int k = 0; k < 64; k += 4) {
        float4 av = *reinterpret_cast<const float4*>(a + k);
#pragma unroll
        for (int kk = 0; kk < 4; kk++) {
            float aval = (&av.x)[kk];
            float4 wv = *reinterpret_cast<const float4*>(&Ws[(k + kk) * F + cg * 4]);
            acc.x = fmaf(aval, wv.x, acc.x);
            acc.y = fmaf(aval, wv.y, acc.y);
            acc.z = fmaf(aval, wv.z, acc.z);
            acc.w = fmaf(aval, wv.w, acc.w);
        }
    }
    if (SWISH) {
        float4 b = *reinterpret_cast<const float4*>(bias + cg * 4);
        acc.x += b.x; acc.y += b.y; acc.z += b.z; acc.w += b.w;
        acc.x = acc.x / (1.f + __expf(-acc.x));
        acc.y = acc.y / (1.f + __expf(-acc.y));
        acc.z = acc.z / (1.f + __expf(-acc.z));
        acc.w = acc.w / (1.f + __expf(-acc.w));
    }
    *reinterpret_cast<float4*>(out + row * F + cg * 4) = acc;
}

// -------------------- CSR aggregation + bias + swish ------------------------
// one warp per node; each lane owns a float2 (64 features / 32 lanes)
__global__ void agg_swish_kernel(const float* __restrict__ h,
                                 const float* __restrict__ bias,
                                 float* __restrict__ out) {
    int warp = (blockIdx.x * blockDim.x + threadIdx.x) >> 5;
    int lane = threadIdx.x & 31;
    if (warp >= N_NODES) return;
    int beg = g_rowptr[warp];
    int end = g_rowptr[warp + 1];
    const float2* hp = reinterpret_cast<const float2*>(h);
    float2 acc = make_float2(0.f, 0.f);
    for (int e = beg; e < end; e++) {
        int   s = g_src[e];       // uniform across warp -> broadcast
        float w = g_w[e];
        float2 v = hp[s * 32 + lane];
        acc.x = fmaf(w, v.x, acc.x);
        acc.y = fmaf(w, v.y, acc.y);
    }
    float2 b = reinterpret_cast<const float2*>(bias)[lane];
    float ax = acc.x + b.x;
    float ay = acc.y + b.y;
    ax = ax / (1.f + __expf(-ax));
    ay = ay / (1.f + __expf(-ay));
    reinterpret_cast<float2*>(out)[warp * 32 + lane] = make_float2(ax, ay);
}

// ------------------------------- output head --------------------------------
// out[n] = sigmoid(hid[n, :100] @ Wo + bo); one warp per node
__global__ void head_kernel(const float* __restrict__ hid,
                            const float* __restrict__ Wo,
                            const float* __restrict__ bo,
                            float* __restrict__ out) {
    int warp = (blockIdx.x * blockDim.x + threadIdx.x) >> 5;
    int lane = threadIdx.x & 31;
    if (warp >= N_NODES) return;
    const float* row = hid + warp * 100;
    float s = 0.f;
#pragma unroll
    for (int j = lane; j < 100; j += 32) s = fmaf(row[j], Wo[j], s);
#pragma unroll
    for (int o = 16; o; o >>= 1) s += __shfl_down_sync(0xffffffffu, s, o);
    if (lane == 0) out[warp] = 1.f / (1.f + __expf(-(s + bo[0])));
}

// -------------------------------- launcher ----------------------------------
extern "C" void kernel_launch(void* const* d_in, const int* in_sizes, int n_in,
                              void* d_out, int out_size) {
    const float* x    = (const float*)d_in[0];
    const int*   esrc = (const int*)  d_in[1];
    const int*   edst = (const int*)  d_in[2];
    const float* ew   = (const float*)d_in[3];
    const float* W1   = (const float*)d_in[4];
    const float* b1   = (const float*)d_in[5];
    const float* W2   = (const float*)d_in[6];
    const float* b2   = (const float*)d_in[7];
    const float* Wd   = (const float*)d_in[8];
    const float* bd   = (const float*)d_in[9];
    const float* Wo   = (const float*)d_in[10];
    const float* bo   = (const float*)d_in[11];
    float* out = (float*)d_out;

    float *h1, *h2, *hid;
    cudaGetSymbolAddress((void**)&h1,  g_h1);
    cudaGetSymbolAddress((void**)&h2,  g_h2);
    cudaGetSymbolAddress((void**)&hid, g_hid);

    // --- CSR build (reused by both GCN layers) ---
    zero_deg_kernel<<<(N_NODES + 255) / 256, 256>>>();
    hist_kernel<<<(N_EDGES + 255) / 256, 256>>>(edst);
    scan_kernel<<<1, 1024>>>();
    scatter_kernel<<<(N_EDGES + 255) / 256, 256>>>(esrc, edst, ew);

    const int aggBlocks = (N_NODES * 32 + 255) / 256;

    // --- layer 1: h1 = x @ W1 ; h2 = swish(agg(h1) + b1) ---
    gemm_kernel<64, false><<<(N_NODES + 15) / 16, dim3(16, 16)>>>(x, W1, nullptr, h1);
    agg_swish_kernel<<<aggBlocks, 256>>>(h1, b1, h2);

    // --- layer 2: h1 = h2 @ W2 ; h2 = swish(agg(h1) + b2) ---
    gemm_kernel<64, false><<<(N_NODES + 15) / 16, dim3(16, 16)>>>(h2, W2, nullptr, h1);
    agg_swish_kernel<<<aggBlocks, 256>>>(h1, b2, h2);

    // --- dense head: hid = swish(h2 @ Wd + bd); out = sigmoid(hid @ Wo + bo) ---
    gemm_kernel<100, true><<<(N_NODES + 7) / 8, dim3(25, 8)>>>(h2, Wd, bd, hid);
    head_kernel<<<aggBlocks, 256>>>(hid, Wo, bo, out);
}

// round 2
// speedup vs baseline: 2.0685x; 2.0685x over previous
#include <cuda_runtime.h>
#include <cuda_bf16.h>

#define N_NODES 50000
#define N_EDGES 800000
#define SCAN_CHUNK 2048
#define SCAN_NB    25          // ceil(50000/2048)

// -------- scratch (static device allocations; no cudaMalloc allowed) --------
__device__ float g_h1[N_NODES * 64];
__device__ float g_h2[N_NODES * 64];
__device__ float g_hid[N_NODES * 100];
__device__ int   g_deg[N_NODES];
__device__ int   g_rowptr[N_NODES + 1];
__device__ int   g_cursor[N_NODES];
__device__ int   g_src[N_EDGES];
__device__ float g_w[N_EDGES];
__device__ int   g_bsum[SCAN_NB];
__device__ int   g_boff[SCAN_NB];

// ---------------------------- CSR construction -----------------------------
__global__ void zero_deg_kernel() {
    int i = blockIdx.x * blockDim.x + threadIdx.x;
    if (i < N_NODES) g_deg[i] = 0;
}

__global__ void hist_kernel(const int* __restrict__ dst) {
    int base = (blockIdx.x * blockDim.x + threadIdx.x) * 4;
#pragma unroll
    for (int j = 0; j < 4; j++) {
        int i = base + j;
        if (i < N_EDGES) atomicAdd(&g_deg[dst[i]], 1);
    }
}

// pass 1: per-block partial sums of degrees
__global__ void scan_partial_kernel() {
    __shared__ int red[256];
    int b = blockIdx.x, t = threadIdx.x;
    int base = b * SCAN_CHUNK;
    int sum = 0;
    for (int i = t; i < SCAN_CHUNK; i += 256) {
        int idx = base + i;
        if (idx < N_NODES) sum += g_deg[idx];
    }
    red[t] = sum;
    __syncthreads();
    for (int o = 128; o; o >>= 1) {
        if (t < o) red[t] += red[t + o];
        __syncthreads();
    }
    if (t == 0) g_bsum[b] = red[0];
}

// pass 2: one warp scans the block sums
__global__ void scan_bsum_kernel() {
    int t = threadIdx.x;
    int v = (t < SCAN_NB) ? g_bsum[t] : 0;
    int incl = v;
#pragma unroll
    for (int o = 1; o < 32; o <<= 1) {
        int u = __shfl_up_sync(0xffffffffu, incl, o);
        if (t >= o) incl += u;
    }
    if (t < SCAN_NB) g_boff[t] = incl - v;
    if (t == SCAN_NB - 1) g_rowptr[N_NODES] = incl;
}

// pass 3: full exclusive scan, write rowptr + cursor
__global__ void scan_final_kernel() {
    __shared__ int sdeg[SCAN_CHUNK];
    __shared__ int tsum[256];
    int b = blockIdx.x, t = threadIdx.x;
    int base = b * SCAN_CHUNK;
    for (int i = t; i < SCAN_CHUNK; i += 256) {
        int idx = base + i;
        sdeg[i] = (idx < N_NODES) ? g_deg[idx] : 0;
    }
    __syncthreads();
    int off = t * 8;
    int run = 0;
#pragma unroll
    for (int j = 0; j < 8; j++) run += sdeg[off + j];
    tsum[t] = run;
    __syncthreads();
    for (int o = 1; o < 256; o <<= 1) {
        int v = (t >= o) ? tsum[t - o] : 0;
        __syncthreads();
        tsum[t] += v;
        __syncthreads();
    }
    run = g_boff[b] + ((t > 0) ? tsum[t - 1] : 0);
#pragma unroll
    for (int j = 0; j < 8; j++) {
        int d = sdeg[off + j];
        sdeg[off + j] = run;
        run += d;
    }
    __syncthreads();
    for (int i = t; i < SCAN_CHUNK; i += 256) {
        int idx = base + i;
        if (idx < N_NODES) {
            int v = sdeg[i];
            g_rowptr[idx] = v;
            g_cursor[idx] = v;
        }
    }
}

__global__ void scatter_kernel(const int* __restrict__ src,
                               const int* __restrict__ dst,
                               const float* __restrict__ w) {
    int base = (blockIdx.x * blockDim.x + threadIdx.x) * 4;
#pragma unroll
    for (int j = 0; j < 4; j++) {
        int i = base + j;
        if (i < N_EDGES) {
            int pos = atomicAdd(&g_cursor[dst[i]], 1);
            g_src[pos] = src[i];
            g_w[pos]   = w[i];
        }
    }
}

// ----------------------- register-tiled GEMM -------------------------------
// tile: 64 rows x F cols; blockDim (F/4, 8); each thread 8 rows x 4 cols.
// A staged TRANSPOSED in smem (Ast[k][row]) so a-loads are LDS.128.
template<int F, bool SWISH>
__global__ void gemm_tiled(const float* __restrict__ A,
                           const float* __restrict__ W,
                           const float* __restrict__ bias,
                           float* __restrict__ out) {
    constexpr int BX  = F / 4;
    constexpr int NTH = BX * 8;
    constexpr int WS  = F + 4;            // pad to dodge bank conflicts
    __shared__ float Ast[64][68];
    __shared__ float Ws[64][WS];

    int tid = threadIdx.y * BX + threadIdx.x;
    int row0 = blockIdx.x * 64;

    // stage W
    for (int i = tid; i < 64 * F; i += NTH)
        Ws[i / F][i % F] = W[i];
    // stage A transposed (coalesced global reads)
    for (int i = tid; i < 64 * 64; i += NTH) {
        int r = i >> 6, k = i & 63;
        int grow = row0 + r;
        Ast[k][r] = (grow < N_NODES) ? A[grow * 64 + k] : 0.f;
    }
    __syncthreads();

    int tx = threadIdx.x, ty = threadIdx.y;
    float acc[8][4];
#pragma unroll
    for (int r = 0; r < 8; r++)
#pragma unroll
        for (int c = 0; c < 4; c++) acc[r][c] = 0.f;

#pragma unroll 4
    for (int k = 0; k < 64; k++) {
        float4 wv = *reinterpret_cast<const float4*>(&Ws[k][tx * 4]);
        float4 a0 = *reinterpret_cast<const float4*>(&Ast[k][ty * 8]);
        float4 a1 = *reinterpret_cast<const float4*>(&Ast[k][ty * 8 + 4]);
        float av[8] = {a0.x, a0.y, a0.z, a0.w, a1.x, a1.y, a1.z, a1.w};
#pragma unroll
        for (int r = 0; r < 8; r++) {
            acc[r][0] = fmaf(av[r], wv.x, acc[r][0]);
            acc[r][1] = fmaf(av[r], wv.y, acc[r][1]);
            acc[r][2] = fmaf(av[r], wv.z, acc[r][2]);
            acc[r][3] = fmaf(av[r], wv.w, acc[r][3]);
        }
    }

    float4 bv = make_float4(0.f, 0.f, 0.f, 0.f);
    if (SWISH) bv = *reinterpret_cast<const float4*>(bias + tx * 4);
#pragma unroll
    for (int r = 0; r < 8; r++) {
        int grow = row0 + ty * 8 + r;
        if (grow >= N_NODES) break;
        float4 o;
        o.x = acc[r][0]; o.y = acc[r][1]; o.z = acc[r][2]; o.w = acc[r][3];
        if (SWISH) {
            o.x += bv.x; o.y += bv.y; o.z += bv.z; o.w += bv.w;
            o.x = o.x / (1.f + __expf(-o.x));
            o.y = o.y / (1.f + __expf(-o.y));
            o.z = o.z / (1.f + __expf(-o.z));
            o.w = o.w / (1.f + __expf(-o.w));
        }
        *reinterpret_cast<float4*>(out + grow * F + tx * 4) = o;
    }
}

// -------------------- CSR aggregation + bias + swish ------------------------
// one warp per node; lane owns float2; 4x unrolled for MLP
__global__ void agg_swish_kernel(const float* __restrict__ h,
                                 const float* __restrict__ bias,
                                 float* __restrict__ out) {
    int warp = (blockIdx.x * blockDim.x + threadIdx.x) >> 5;
    int lane = threadIdx.x & 31;
    if (warp >= N_NODES) return;
    int beg = g_rowptr[warp];
    int end = g_rowptr[warp + 1];
    const float2* hp = reinterpret_cast<const float2*>(h);
    float2 acc = make_float2(0.f, 0.f);
    int e = beg;
    for (; e + 4 <= end; e += 4) {
        int   s0 = g_src[e],   s1 = g_src[e+1], s2 = g_src[e+2], s3 = g_src[e+3];
        float w0 = g_w[e],     w1 = g_w[e+1],   w2 = g_w[e+2],   w3 = g_w[e+3];
        float2 v0 = hp[s0 * 32 + lane];
        float2 v1 = hp[s1 * 32 + lane];
        float2 v2 = hp[s2 * 32 + lane];
        float2 v3 = hp[s3 * 32 + lane];
        acc.x = fmaf(w0, v0.x, acc.x); acc.y = fmaf(w0, v0.y, acc.y);
        acc.x = fmaf(w1, v1.x, acc.x); acc.y = fmaf(w1, v1.y, acc.y);
        acc.x = fmaf(w2, v2.x, acc.x); acc.y = fmaf(w2, v2.y, acc.y);
        acc.x = fmaf(w3, v3.x, acc.x); acc.y = fmaf(w3, v3.y, acc.y);
    }
    for (; e < end; e++) {
        int   s = g_src[e];
        float w = g_w[e];
        float2 v = hp[s * 32 + lane];
        acc.x = fmaf(w, v.x, acc.x);
        acc.y = fmaf(w, v.y, acc.y);
    }
    float2 b = reinterpret_cast<const float2*>(bias)[lane];
    float ax = acc.x + b.x;
    float ay = acc.y + b.y;
    ax = ax / (1.f + __expf(-ax));
    ay = ay / (1.f + __expf(-ay));
    reinterpret_cast<float2*>(out)[warp * 32 + lane] = make_float2(ax, ay);
}

// ------------------------------- output head --------------------------------
__global__ void head_kernel(const float* __restrict__ hid,
                            const float* __restrict__ Wo,
                            const float* __restrict__ bo,
                            float* __restrict__ out) {
    int warp = (blockIdx.x * blockDim.x + threadIdx.x) >> 5;
    int lane = threadIdx.x & 31;
    if (warp >= N_NODES) return;
    const float* row = hid + warp * 100;
    float s = 0.f;
#pragma unroll
    for (int j = lane; j < 100; j += 32) s = fmaf(row[j], Wo[j], s);
#pragma unroll
    for (int o = 16; o; o >>= 1) s += __shfl_down_sync(0xffffffffu, s, o);
    if (lane == 0) out[warp] = 1.f / (1.f + __expf(-(s + bo[0])));
}

// -------------------------------- launcher ----------------------------------
extern "C" void kernel_launch(void* const* d_in, const int* in_sizes, int n_in,
                              void* d_out, int out_size) {
    const float* x    = (const float*)d_in[0];
    const int*   esrc = (const int*)  d_in[1];
    const int*   edst = (const int*)  d_in[2];
    const float* ew   = (const float*)d_in[3];
    const float* W1   = (const float*)d_in[4];
    const float* b1   = (const float*)d_in[5];
    const float* W2   = (const float*)d_in[6];
    const float* b2   = (const float*)d_in[7];
    const float* Wd   = (const float*)d_in[8];
    const float* bd   = (const float*)d_in[9];
    const float* Wo   = (const float*)d_in[10];
    const float* bo   = (const float*)d_in[11];
    float* out = (float*)d_out;

    float *h1, *h2, *hid;
    cudaGetSymbolAddress((void**)&h1,  g_h1);
    cudaGetSymbolAddress((void**)&h2,  g_h2);
    cudaGetSymbolAddress((void**)&hid, g_hid);

    // --- CSR build ---
    zero_deg_kernel<<<(N_NODES + 255) / 256, 256>>>();
    hist_kernel<<<(N_EDGES / 4 + 255) / 256, 256>>>(edst);
    scan_partial_kernel<<<SCAN_NB, 256>>>();
    scan_bsum_kernel<<<1, 32>>>();
    scan_final_kernel<<<SCAN_NB, 256>>>();
    scatter_kernel<<<(N_EDGES / 4 + 255) / 256, 256>>>(esrc, edst, ew);

    const int aggBlocks  = (N_NODES * 32 + 255) / 256;
    const int gemmBlocks = (N_NODES + 63) / 64;

    // --- layer 1 ---
    gemm_tiled<64, false><<<gemmBlocks, dim3(16, 8)>>>(x, W1, nullptr, h1);
    agg_swish_kernel<<<aggBlocks, 256>>>(h1, b1, h2);

    // --- layer 2 ---
    gemm_tiled<64, false><<<gemmBlocks, dim3(16, 8)>>>(h2, W2, nullptr, h1);
    agg_swish_kernel<<<aggBlocks, 256>>>(h1, b2, h2);

    // --- dense head ---
    gemm_tiled<100, true><<<gemmBlocks, dim3(25, 8)>>>(h2, Wd, bd, hid);
    head_kernel<<<aggBlocks, 256>>>(hid, Wo, bo, out);
}

// round 3
// speedup vs baseline: 3.0230x; 1.4615x over previous
#include <cuda_runtime.h>
#include <cuda_fp16.h>

#define N_NODES 50000
#define N_EDGES 800000
#define SCAN_T  1024
#define CHUNK   49           // 1024*49 = 50176 >= 50000
#define SCAN_PAD (SCAN_T * CHUNK)

// -------- scratch (static device allocations; no cudaMalloc allowed) --------
__device__ __half g_h1h[N_NODES * 64];   // GEMM out (half) -> agg gather input
__device__ float  g_h2[N_NODES * 64];    // agg out (fp32) -> next GEMM input
__device__ int    g_deg[N_NODES];
__device__ int    g_rowptr[N_NODES + 1];
__device__ int    g_cursor[N_NODES];
__device__ int    g_src[N_EDGES];
__device__ float  g_w[N_EDGES];

struct alignas(8) H4 { __half2 a, b; };

// ---------------------------- CSR construction -----------------------------
__global__ void hist_kernel(const int* __restrict__ dst) {
    int base = (blockIdx.x * blockDim.x + threadIdx.x) * 4;
#pragma unroll
    for (int j = 0; j < 4; j++) {
        int i = base + j;
        if (i < N_EDGES) atomicAdd(&g_deg[dst[i]], 1);
    }
}

// one block, whole scan in smem (200KB dynamic)
__global__ void scan_fused_kernel() {
    extern __shared__ int sdeg[];          // SCAN_PAD ints
    __shared__ int warpsum[32];
    int t = threadIdx.x;
    for (int i = t; i < SCAN_PAD; i += SCAN_T)
        sdeg[i] = (i < N_NODES) ? g_deg[i] : 0;
    __syncthreads();

    int base = t * CHUNK;
    int sum = 0;
    for (int j = 0; j < CHUNK; j++) sum += sdeg[base + j];

    int lane = t & 31, wid = t >> 5;
    int incl = sum;
#pragma unroll
    for (int o = 1; o < 32; o <<= 1) {
        int u = __shfl_up_sync(0xffffffffu, incl, o);
        if (lane >= o) incl += u;
    }
    if (lane == 31) warpsum[wid] = incl;
    __syncthreads();
    if (wid == 0) {
        int v = warpsum[lane];
        int wi = v;
#pragma unroll
        for (int o = 1; o < 32; o <<= 1) {
            int u = __shfl_up_sync(0xffffffffu, wi, o);
            if (lane >= o) wi += u;
        }
        warpsum[lane] = wi - v;            // exclusive
        if (lane == 31) g_rowptr[N_NODES] = wi;
    }
    __syncthreads();

    int run = warpsum[wid] + (incl - sum); // exclusive offset for this thread
    for (int j = 0; j < CHUNK; j++) {
        int d = sdeg[base + j];
        sdeg[base + j] = run;
        run += d;
    }
    __syncthreads();
    for (int i = t; i < N_NODES; i += SCAN_T) {
        int v = sdeg[i];
        g_rowptr[i] = v;
        g_cursor[i] = v;
    }
}

__global__ void scatter_kernel(const int* __restrict__ src,
                               const int* __restrict__ dst,
                               const float* __restrict__ w) {
    int base = (blockIdx.x * blockDim.x + threadIdx.x) * 4;
#pragma unroll
    for (int j = 0; j < 4; j++) {
        int i = base + j;
        if (i < N_EDGES) {
            int pos = atomicAdd(&g_cursor[dst[i]], 1);
            g_src[pos] = src[i];
            g_w[pos]   = w[i];
        }
    }
}

// ------------------- register-tiled GEMM (64x64, half out) ------------------
// tile 64 rows x 64 cols; blockDim (16,8); thread: 8 rows x 4 cols
__global__ void gemm64h_kernel(const float* __restrict__ A,
                               const float* __restrict__ W,
                               __half* __restrict__ outh) {
    __shared__ float Ast[64][68];
    __shared__ float Ws[64][68];
    int tid = threadIdx.y * 16 + threadIdx.x;
    int row0 = blockIdx.x * 64;

    for (int i = tid; i < 64 * 64; i += 128)
        Ws[i >> 6][i & 63] = W[i];
    for (int i = tid; i < 64 * 64; i += 128) {
        int r = i >> 6, k = i & 63;
        int grow = row0 + r;
        Ast[k][r] = (grow < N_NODES) ? A[grow * 64 + k] : 0.f;
    }
    __syncthreads();

    int tx = threadIdx.x, ty = threadIdx.y;
    float acc[8][4];
#pragma unroll
    for (int r = 0; r < 8; r++)
#pragma unroll
        for (int c = 0; c < 4; c++) acc[r][c] = 0.f;

#pragma unroll 4
    for (int k = 0; k < 64; k++) {
        float4 wv = *reinterpret_cast<const float4*>(&Ws[k][tx * 4]);
        float4 a0 = *reinterpret_cast<const float4*>(&Ast[k][ty * 8]);
        float4 a1 = *reinterpret_cast<const float4*>(&Ast[k][ty * 8 + 4]);
        float av[8] = {a0.x, a0.y, a0.z, a0.w, a1.x, a1.y, a1.z, a1.w};
#pragma unroll
        for (int r = 0; r < 8; r++) {
            acc[r][0] = fmaf(av[r], wv.x, acc[r][0]);
            acc[r][1] = fmaf(av[r], wv.y, acc[r][1]);
            acc[r][2] = fmaf(av[r], wv.z, acc[r][2]);
            acc[r][3] = fmaf(av[r], wv.w, acc[r][3]);
        }
    }
#pragma unroll
    for (int r = 0; r < 8; r++) {
        int grow = row0 + ty * 8 + r;
        if (grow >= N_NODES) break;
        H4 o;
        o.a = __floats2half2_rn(acc[r][0], acc[r][1]);
        o.b = __floats2half2_rn(acc[r][2], acc[r][3]);
        *reinterpret_cast<H4*>(outh + grow * 64 + tx * 4) = o;
    }
}

// -------------------- CSR aggregation + bias + swish ------------------------
// one warp per node; lane owns half2 (features 2l,2l+1); fp32 accumulate
__global__ void agg_swish_kernel(const __half2* __restrict__ hp,
                                 const float* __restrict__ bias,
                                 float* __restrict__ out) {
    int warp = (blockIdx.x * blockDim.x + threadIdx.x) >> 5;
    int lane = threadIdx.x & 31;
    if (warp >= N_NODES) return;
    int beg = g_rowptr[warp];
    int end = g_rowptr[warp + 1];
    float2 acc = make_float2(0.f, 0.f);
    int e = beg;
    for (; e + 4 <= end; e += 4) {
        int   s0 = g_src[e],   s1 = g_src[e+1], s2 = g_src[e+2], s3 = g_src[e+3];
        float w0 = g_w[e],     w1 = g_w[e+1],   w2 = g_w[e+2],   w3 = g_w[e+3];
        float2 v0 = __half22float2(hp[s0 * 32 + lane]);
        float2 v1 = __half22float2(hp[s1 * 32 + lane]);
        float2 v2 = __half22float2(hp[s2 * 32 + lane]);
        float2 v3 = __half22float2(hp[s3 * 32 + lane]);
        acc.x = fmaf(w0, v0.x, acc.x); acc.y = fmaf(w0, v0.y, acc.y);
        acc.x = fmaf(w1, v1.x, acc.x); acc.y = fmaf(w1, v1.y, acc.y);
        acc.x = fmaf(w2, v2.x, acc.x); acc.y = fmaf(w2, v2.y, acc.y);
        acc.x = fmaf(w3, v3.x, acc.x); acc.y = fmaf(w3, v3.y, acc.y);
    }
    for (; e < end; e++) {
        int   s = g_src[e];
        float w = g_w[e];
        float2 v = __half22float2(hp[s * 32 + lane]);
        acc.x = fmaf(w, v.x, acc.x);
        acc.y = fmaf(w, v.y, acc.y);
    }
    float2 b = reinterpret_cast<const float2*>(bias)[lane];
    float ax = acc.x + b.x;
    float ay = acc.y + b.y;
    ax = ax / (1.f + __expf(-ax));
    ay = ay / (1.f + __expf(-ay));
    reinterpret_cast<float2*>(out)[warp * 32 + lane] = make_float2(ax, ay);
}

// --------------- fused dense(100, swish) + dense(1, sigmoid) ----------------
// tile 64 rows x 100 cols; blockDim (25,8); thread: 8 rows x 4 cols
__global__ void gemm100_head_kernel(const float* __restrict__ A,
                                    const float* __restrict__ Wd,
                                    const float* __restrict__ bd,
                                    const float* __restrict__ Wo,
                                    const float* __restrict__ bo,
                                    float* __restrict__ out) {
    __shared__ float Ast[64][68];
    __shared__ float Ws[64][104];
    __shared__ float woS[100];
    __shared__ float part[64][26];
    int tid = threadIdx.y * 25 + threadIdx.x;
    int row0 = blockIdx.x * 64;

    for (int i = tid; i < 64 * 100; i += 200)
        Ws[i / 100][i % 100] = Wd[i];
    for (int i = tid; i < 64 * 64; i += 200) {
        int r = i >> 6, k = i & 63;
        int grow = row0 + r;
        Ast[k][r] = (grow < N_NODES) ? A[grow * 64 + k] : 0.f;
    }
    if (tid < 100) woS[tid] = Wo[tid];
    __syncthreads();

    int tx = threadIdx.x, ty = threadIdx.y;
    float acc[8][4];
#pragma unroll
    for (int r = 0; r < 8; r++)
#pragma unroll
        for (int c = 0; c < 4; c++) acc[r][c] = 0.f;

#pragma unroll 4
    for (int k = 0; k < 64; k++) {
        float4 wv = *reinterpret_cast<const float4*>(&Ws[k][tx * 4]);
        float4 a0 = *reinterpret_cast<const float4*>(&Ast[k][ty * 8]);
        float4 a1 = *reinterpret_cast<const float4*>(&Ast[k][ty * 8 + 4]);
        float av[8] = {a0.x, a0.y, a0.z, a0.w, a1.x, a1.y, a1.z, a1.w};
#pragma unroll
        for (int r = 0; r < 8; r++) {
            acc[r][0] = fmaf(av[r], wv.x, acc[r][0]);
            acc[r][1] = fmaf(av[r], wv.y, acc[r][1]);
            acc[r][2] = fmaf(av[r], wv.z, acc[r][2]);
            acc[r][3] = fmaf(av[r], wv.w, acc[r][3]);
        }
    }

    // bias + swish in registers, then partial head dot per thread
    float4 bv = *reinterpret_cast<const float4*>(bd + tx * 4);
    float4 wo4 = *reinterpret_cast<const float4*>(&woS[tx * 4]);
#pragma unroll
    for (int r = 0; r < 8; r++) {
        float v0 = acc[r][0] + bv.x;
        float v1 = acc[r][1] + bv.y;
        float v2 = acc[r][2] + bv.z;
        float v3 = acc[r][3] + bv.w;
        v0 = v0 / (1.f + __expf(-v0));
        v1 = v1 / (1.f + __expf(-v1));
        v2 = v2 / (1.f + __expf(-v2));
        v3 = v3 / (1.f + __expf(-v3));
        float p = v0 * wo4.x + v1 * wo4.y + v2 * wo4.z + v3 * wo4.w;
        part[ty * 8 + r][tx] = p;
    }
    __syncthreads();

    if (tid < 64) {
        int grow = row0 + tid;
        if (grow < N_NODES) {
            float s = 0.f;
#pragma unroll
            for (int j = 0; j < 25; j++) s += part[tid][j];
            out[grow] = 1.f / (1.f + __expf(-(s + bo[0])));
        }
    }
}

// -------------------------------- launcher ----------------------------------
extern "C" void kernel_launch(void* const* d_in, const int* in_sizes, int n_in,
                              void* d_out, int out_size) {
    const float* x    = (const float*)d_in[0];
    const int*   esrc = (const int*)  d_in[1];
    const int*   edst = (const int*)  d_in[2];
    const float* ew   = (const float*)d_in[3];
    const float* W1   = (const float*)d_in[4];
    const float* b1   = (const float*)d_in[5];
    const float* W2   = (const float*)d_in[6];
    const float* b2   = (const float*)d_in[7];
    const float* Wd   = (const float*)d_in[8];
    const float* bd   = (const float*)d_in[9];
    const float* Wo   = (const float*)d_in[10];
    const float* bo   = (const float*)d_in[11];
    float* out = (float*)d_out;

    __half* h1h;  float* h2;  int* degp;
    cudaGetSymbolAddress((void**)&h1h,  g_h1h);
    cudaGetSymbolAddress((void**)&h2,   g_h2);
    cudaGetSymbolAddress((void**)&degp, g_deg);

    static bool attr_set = false;
    if (!attr_set) {
        cudaFuncSetAttribute(scan_fused_kernel,
                             cudaFuncAttributeMaxDynamicSharedMemorySize,
                             SCAN_PAD * (int)sizeof(int));
        attr_set = true;
    }

    // --- CSR build ---
    cudaMemsetAsync(degp, 0, N_NODES * sizeof(int));
    hist_kernel<<<(N_EDGES / 4 + 255) / 256, 256>>>(edst);
    scan_fused_kernel<<<1, SCAN_T, SCAN_PAD * sizeof(int)>>>();
    scatter_kernel<<<(N_EDGES / 4 + 255) / 256, 256>>>(esrc, edst, ew);

    const int aggBlocks  = (N_NODES * 32 + 255) / 256;
    const int gemmBlocks = (N_NODES + 63) / 64;

    // --- layer 1 ---
    gemm64h_kernel<<<gemmBlocks, dim3(16, 8)>>>(x, W1, h1h);
    agg_swish_kernel<<<aggBlocks, 256>>>((const __half2*)h1h, b1, h2);

    // --- layer 2 ---
    gemm64h_kernel<<<gemmBlocks, dim3(16, 8)>>>(h2, W2, h1h);
    agg_swish_kernel<<<aggBlocks, 256>>>((const __half2*)h1h, b2, h2);

    // --- dense head (fused) ---
    gemm100_head_kernel<<<gemmBlocks, dim3(25, 8)>>>(h2, Wd, bd, Wo, bo, out);
}

// round 4
// speedup vs baseline: 3.2063x; 1.0606x over previous
#include <cuda_runtime.h>
#include <cuda_fp16.h>

#define N_NODES 50000
#define N_EDGES 800000
#define SCAN_T  1024
#define CHUNK   49           // 1024*49 = 50176 >= 50000
#define SCAN_PAD (SCAN_T * CHUNK)

#define GEMM64_SMEM  ((64*132 + 64*72) * 4)
#define HEAD_SMEM    ((64*132 + 64*104 + 128*26 + 128) * 4)

// -------- scratch (static device allocations; no cudaMalloc allowed) --------
__device__ __half g_h1h[N_NODES * 64];   // GEMM out (half) -> agg gather input
__device__ float  g_h2[N_NODES * 64];    // agg out (fp32) -> next GEMM input
__device__ int    g_deg[N_NODES];
__device__ int    g_rowptr[N_NODES + 1];
__device__ int    g_cursor[N_NODES];
__device__ int2   g_edge[N_EDGES];       // (src, weight-bits)

// ---------------------------- CSR construction -----------------------------
__global__ void hist_kernel(const int4* __restrict__ dst4) {
    int i = blockIdx.x * blockDim.x + threadIdx.x;
    if (i < N_EDGES / 4) {
        int4 d = dst4[i];
        atomicAdd(&g_deg[d.x], 1);
        atomicAdd(&g_deg[d.y], 1);
        atomicAdd(&g_deg[d.z], 1);
        atomicAdd(&g_deg[d.w], 1);
    }
}

// one block, whole scan in smem (~200KB dynamic)
__global__ void scan_fused_kernel() {
    extern __shared__ int sdeg[];
    __shared__ int warpsum[32];
    int t = threadIdx.x;
    for (int i = t; i < SCAN_PAD; i += SCAN_T)
        sdeg[i] = (i < N_NODES) ? g_deg[i] : 0;
    __syncthreads();

    int base = t * CHUNK;
    int sum = 0;
    for (int j = 0; j < CHUNK; j++) sum += sdeg[base + j];

    int lane = t & 31, wid = t >> 5;
    int incl = sum;
#pragma unroll
    for (int o = 1; o < 32; o <<= 1) {
        int u = __shfl_up_sync(0xffffffffu, incl, o);
        if (lane >= o) incl += u;
    }
    if (lane == 31) warpsum[wid] = incl;
    __syncthreads();
    if (wid == 0) {
        int v = warpsum[lane];
        int wi = v;
#pragma unroll
        for (int o = 1; o < 32; o <<= 1) {
            int u = __shfl_up_sync(0xffffffffu, wi, o);
            if (lane >= o) wi += u;
        }
        warpsum[lane] = wi - v;
        if (lane == 31) g_rowptr[N_NODES] = wi;
    }
    __syncthreads();

    int run = warpsum[wid] + (incl - sum);
    for (int j = 0; j < CHUNK; j++) {
        int d = sdeg[base + j];
        sdeg[base + j] = run;
        run += d;
    }
    __syncthreads();
    for (int i = t; i < N_NODES; i += SCAN_T) {
        int v = sdeg[i];
        g_rowptr[i] = v;
        g_cursor[i] = v;
    }
}

__global__ void scatter_kernel(const int4* __restrict__ src4,
                               const int4* __restrict__ dst4,
                               const float4* __restrict__ w4) {
    int i = blockIdx.x * blockDim.x + threadIdx.x;
    if (i >= N_EDGES / 4) return;
    int4   s = src4[i];
    int4   d = dst4[i];
    float4 w = w4[i];
    int p0 = atomicAdd(&g_cursor[d.x], 1);
    int p1 = atomicAdd(&g_cursor[d.y], 1);
    int p2 = atomicAdd(&g_cursor[d.z], 1);
    int p3 = atomicAdd(&g_cursor[d.w], 1);
    g_edge[p0] = make_int2(s.x, __float_as_int(w.x));
    g_edge[p1] = make_int2(s.y, __float_as_int(w.y));
    g_edge[p2] = make_int2(s.z, __float_as_int(w.z));
    g_edge[p3] = make_int2(s.w, __float_as_int(w.w));
}

// ------------- register-tiled GEMM 128x64, 8x8 per thread, half out ---------
// blockDim (8,16) = 128 threads. Dynamic smem: Ast[64][132] + Ws[64][72]
__global__ void gemm64h_kernel(const float* __restrict__ A,
                               const float* __restrict__ W,
                               __half* __restrict__ outh) {
    extern __shared__ float sm[];
    float* Ast = sm;                 // [64][132], transposed A
    float* Ws  = sm + 64 * 132;      // [64][72]
    const int tx = threadIdx.x;      // 0..7  (cols)
    const int ty = threadIdx.y;      // 0..15 (rows)
    const int tid = ty * 8 + tx;
    const int row0 = blockIdx.x * 128;

    // stage W (4096 floats), vectorized
    for (int i = tid * 4; i < 4096; i += 512) {
        int k = i >> 6, c = i & 63;
        float4 v = *reinterpret_cast<const float4*>(W + i);
        *reinterpret_cast<float4*>(&Ws[k * 72 + c]) = v;
    }
    // stage A transposed: coalesced LDG.128, 4 scalar STS
    for (int i = tid * 4; i < 8192; i += 512) {
        int r = i >> 6, k = i & 63;
        int grow = row0 + r;
        float4 v = (grow < N_NODES)
                 ? *reinterpret_cast<const float4*>(A + grow * 64 + k)
                 : make_float4(0.f, 0.f, 0.f, 0.f);
        Ast[(k + 0) * 132 + r] = v.x;
        Ast[(k + 1) * 132 + r] = v.y;
        Ast[(k + 2) * 132 + r] = v.z;
        Ast[(k + 3) * 132 + r] = v.w;
    }
    __syncthreads();

    float acc[8][8];
#pragma unroll
    for (int r = 0; r < 8; r++)
#pragma unroll
        for (int c = 0; c < 8; c++) acc[r][c] = 0.f;

#pragma unroll 2
    for (int k = 0; k < 64; k++) {
        float4 a0 = *reinterpret_cast<const float4*>(&Ast[k * 132 + ty * 8]);
        float4 a1 = *reinterpret_cast<const float4*>(&Ast[k * 132 + ty * 8 + 4]);
        float4 w0 = *reinterpret_cast<const float4*>(&Ws[k * 72 + tx * 8]);
        float4 w1 = *reinterpret_cast<const float4*>(&Ws[k * 72 + tx * 8 + 4]);
        float av[8] = {a0.x, a0.y, a0.z, a0.w, a1.x, a1.y, a1.z, a1.w};
        float wv[8] = {w0.x, w0.y, w0.z, w0.w, w1.x, w1.y, w1.z, w1.w};
#pragma unroll
        for (int r = 0; r < 8; r++)
#pragma unroll
            for (int c = 0; c < 8; c++)
                acc[r][c] = fmaf(av[r], wv[c], acc[r][c]);
    }

#pragma unroll
    for (int r = 0; r < 8; r++) {
        int grow = row0 + ty * 8 + r;
        if (grow < N_NODES) {
            uint4 o;
            __half2 h0 = __floats2half2_rn(acc[r][0], acc[r][1]);
            __half2 h1 = __floats2half2_rn(acc[r][2], acc[r][3]);
            __half2 h2 = __floats2half2_rn(acc[r][4], acc[r][5]);
            __half2 h3 = __floats2half2_rn(acc[r][6], acc[r][7]);
            o.x = *reinterpret_cast<unsigned*>(&h0);
            o.y = *reinterpret_cast<unsigned*>(&h1);
            o.z = *reinterpret_cast<unsigned*>(&h2);
            o.w = *reinterpret_cast<unsigned*>(&h3);
            *reinterpret_cast<uint4*>(outh + grow * 64 + tx * 8) = o;
        }
    }
}

// -------------------- CSR aggregation + bias + swish ------------------------
// one warp per node; lane owns half2; 8x unroll for MLP
__global__ void agg_swish_kernel(const __half2* __restrict__ hp,
                                 const float* __restrict__ bias,
                                 float* __restrict__ out) {
    int warp = (blockIdx.x * blockDim.x + threadIdx.x) >> 5;
    int lane = threadIdx.x & 31;
    if (warp >= N_NODES) return;
    int beg = g_rowptr[warp];
    int end = g_rowptr[warp + 1];
    float2 acc = make_float2(0.f, 0.f);
    int e = beg;
    for (; e + 8 <= end; e += 8) {
        int2 ed[8];
#pragma unroll
        for (int j = 0; j < 8; j++) ed[j] = g_edge[e + j];
        float2 v[8];
#pragma unroll
        for (int j = 0; j < 8; j++) v[j] = __half22float2(hp[ed[j].x * 32 + lane]);
#pragma unroll
        for (int j = 0; j < 8; j++) {
            float w = __int_as_float(ed[j].y);
            acc.x = fmaf(w, v[j].x, acc.x);
            acc.y = fmaf(w, v[j].y, acc.y);
        }
    }
    for (; e + 2 <= end; e += 2) {
        int2 e0 = g_edge[e], e1 = g_edge[e + 1];
        float2 v0 = __half22float2(hp[e0.x * 32 + lane]);
        float2 v1 = __half22float2(hp[e1.x * 32 + lane]);
        float w0 = __int_as_float(e0.y), w1 = __int_as_float(e1.y);
        acc.x = fmaf(w0, v0.x, acc.x); acc.y = fmaf(w0, v0.y, acc.y);
        acc.x = fmaf(w1, v1.x, acc.x); acc.y = fmaf(w1, v1.y, acc.y);
    }
    if (e < end) {
        int2 e0 = g_edge[e];
        float2 v0 = __half22float2(hp[e0.x * 32 + lane]);
        float w0 = __int_as_float(e0.y);
        acc.x = fmaf(w0, v0.x, acc.x); acc.y = fmaf(w0, v0.y, acc.y);
    }
    float2 b = reinterpret_cast<const float2*>(bias)[lane];
    float ax = acc.x + b.x;
    float ay = acc.y + b.y;
    ax = ax / (1.f + __expf(-ax));
    ay = ay / (1.f + __expf(-ay));
    reinterpret_cast<float2*>(out)[warp * 32 + lane] = make_float2(ax, ay);
}

// --------------- fused dense(100, swish) + dense(1, sigmoid) ----------------
// tile 128 rows x 100 cols; blockDim (25,16)=400; thread 8 rows x 4 cols
__global__ void gemm100_head_kernel(const float* __restrict__ A,
                                    const float* __restrict__ Wd,
                                    const float* __restrict__ bd,
                                    const float* __restrict__ Wo,
                                    const float* __restrict__ bo,
                                    float* __restrict__ out) {
    extern __shared__ float sm[];
    float* Ast  = sm;                       // [64][132]
    float* Ws   = Ast + 64 * 132;           // [64][104]
    float* part = Ws + 64 * 104;            // [128][26]
    float* woS  = part + 128 * 26;          // [100]
    const int tx = threadIdx.x;             // 0..24
    const int ty = threadIdx.y;             // 0..15
    const int tid = ty * 25 + tx;           // 0..399
    const int row0 = blockIdx.x * 128;

    for (int i = tid * 4; i < 6400; i += 1600) {
        int k = i / 100, c = i % 100;       // c in {0,4,...,96}
        float4 v = *reinterpret_cast<const float4*>(Wd + i);
        *reinterpret_cast<float4*>(&Ws[k * 104 + c]) = v;
    }
    for (int i = tid * 4; i < 8192; i += 1600) {
        int r = i >> 6, k = i & 63;
        int grow = row0 + r;
        float4 v = (grow < N_NODES)
                 ? *reinterpret_cast<const float4*>(A + grow * 64 + k)
                 : make_float4(0.f, 0.f, 0.f, 0.f);
        Ast[(k + 0) * 132 + r] = v.x;
        Ast[(k + 1) * 132 + r] = v.y;
        Ast[(k + 2) * 132 + r] = v.z;
        Ast[(k + 3) * 132 + r] = v.w;
    }
    if (tid < 100) woS[tid] = Wo[tid];
    __syncthreads();

    float acc[8][4];
#pragma unroll
    for (int r = 0; r < 8; r++)
#pragma unroll
        for (int c = 0; c < 4; c++) acc[r][c] = 0.f;

#pragma unroll 2
    for (int k = 0; k < 64; k++) {
        float4 wv = *reinterpret_cast<const float4*>(&Ws[k * 104 + tx * 4]);
        float4 a0 = *reinterpret_cast<const float4*>(&Ast[k * 132 + ty * 8]);
        float4 a1 = *reinterpret_cast<const float4*>(&Ast[k * 132 + ty * 8 + 4]);
        float av[8] = {a0.x, a0.y, a0.z, a0.w, a1.x, a1.y, a1.z, a1.w};
#pragma unroll
        for (int r = 0; r < 8; r++) {
            acc[r][0] = fmaf(av[r], wv.x, acc[r][0]);
            acc[r][1] = fmaf(av[r], wv.y, acc[r][1]);
            acc[r][2] = fmaf(av[r], wv.z, acc[r][2]);
            acc[r][3] = fmaf(av[r], wv.w, acc[r][3]);
        }
    }

    float4 bv  = *reinterpret_cast<const float4*>(bd + tx * 4);
    float4 wo4 = *reinterpret_cast<const float4*>(&woS[tx * 4]);
#pragma unroll
    for (int r = 0; r < 8; r++) {
        float v0 = acc[r][0] + bv.x;
        float v1 = acc[r][1] + bv.y;
        float v2 = acc[r][2] + bv.z;
        float v3 = acc[r][3] + bv.w;
        v0 = v0 / (1.f + __expf(-v0));
        v1 = v1 / (1.f + __expf(-v1));
        v2 = v2 / (1.f + __expf(-v2));
        v3 = v3 / (1.f + __expf(-v3));
        part[(ty * 8 + r) * 26 + tx] = v0 * wo4.x + v1 * wo4.y + v2 * wo4.z + v3 * wo4.w;
    }
    __syncthreads();

    if (tid < 128) {
        int grow = row0 + tid;
        if (grow < N_NODES) {
            float s = 0.f;
#pragma unroll
            for (int j = 0; j < 25; j++) s += part[tid * 26 + j];
            out[grow] = 1.f / (1.f + __expf(-(s + bo[0])));
        }
    }
}

// -------------------------------- launcher ----------------------------------
extern "C" void kernel_launch(void* const* d_in, const int* in_sizes, int n_in,
                              void* d_out, int out_size) {
    const float* x    = (const float*)d_in[0];
    const int*   esrc = (const int*)  d_in[1];
    const int*   edst = (const int*)  d_in[2];
    const float* ew   = (const float*)d_in[3];
    const float* W1   = (const float*)d_in[4];
    const float* b1   = (const float*)d_in[5];
    const float* W2   = (const float*)d_in[6];
    const float* b2   = (const float*)d_in[7];
    const float* Wd   = (const float*)d_in[8];
    const float* bd   = (const float*)d_in[9];
    const float* Wo   = (const float*)d_in[10];
    const float* bo   = (const float*)d_in[11];
    float* out = (float*)d_out;

    __half* h1h;  float* h2;  int* degp;
    cudaGetSymbolAddress((void**)&h1h,  g_h1h);
    cudaGetSymbolAddress((void**)&h2,   g_h2);
    cudaGetSymbolAddress((void**)&degp, g_deg);

    cudaFuncSetAttribute(scan_fused_kernel,
                         cudaFuncAttributeMaxDynamicSharedMemorySize,
                         SCAN_PAD * (int)sizeof(int));
    cudaFuncSetAttribute(gemm64h_kernel,
                         cudaFuncAttributeMaxDynamicSharedMemorySize, GEMM64_SMEM);
    cudaFuncSetAttribute(gemm100_head_kernel,
                         cudaFuncAttributeMaxDynamicSharedMemorySize, HEAD_SMEM);

    // --- CSR build ---
    cudaMemsetAsync(degp, 0, N_NODES * sizeof(int));
    hist_kernel<<<(N_EDGES / 4 + 255) / 256, 256>>>((const int4*)edst);
    scan_fused_kernel<<<1, SCAN_T, SCAN_PAD * sizeof(int)>>>();
    scatter_kernel<<<(N_EDGES / 4 + 255) / 256, 256>>>((const int4*)esrc,
                                                       (const int4*)edst,
                                                       (const float4*)ew);

    const int aggBlocks  = (N_NODES * 32 + 255) / 256;
    const int gemmBlocks = (N_NODES + 127) / 128;

    // --- layer 1 ---
    gemm64h_kernel<<<gemmBlocks, dim3(8, 16), GEMM64_SMEM>>>(x, W1, h1h);
    agg_swish_kernel<<<aggBlocks, 256>>>((const __half2*)h1h, b1, h2);

    // --- layer 2 ---
    gemm64h_kernel<<<gemmBlocks, dim3(8, 16), GEMM64_SMEM>>>(h2, W2, h1h);
    agg_swish_kernel<<<aggBlocks, 256>>>((const __half2*)h1h, b2, h2);

    // --- dense head (fused) ---
    gemm100_head_kernel<<<gemmBlocks, dim3(25, 16), HEAD_SMEM>>>(h2, Wd, bd, Wo, bo, out);
}

// round 5
// speedup vs baseline: 3.6304x; 1.1322x over previous
#include <cuda_runtime.h>
#include <cuda_fp16.h>

#define N_NODES 50000
#define N_EDGES 800000
#define SCAN_T  1024
#define CHUNK   49           // 1024*49 = 50176 >= 50000
#define SCAN_PAD (SCAN_T * CHUNK)

#define HEAD_SMEM    ((64*132 + 64*104 + 128*26 + 128) * 4)

// -------- scratch (static device allocations; no cudaMalloc allowed) --------
__device__ __half g_h1h[N_NODES * 64];   // GEMM out (half) -> agg gather input
__device__ float  g_h2[N_NODES * 64];    // agg out (fp32) -> next GEMM input
__device__ int    g_deg[N_NODES];
__device__ int    g_rowptr[N_NODES + 1];
__device__ int    g_cursor[N_NODES];
__device__ int2   g_edge[N_EDGES];       // (src, weight-bits)

// ---------------------------- PTX helpers -----------------------------------
__device__ __forceinline__ unsigned smem_u32(const void* p) {
    return (unsigned)__cvta_generic_to_shared(p);
}
__device__ __forceinline__ void ldsm_x4(unsigned& r0, unsigned& r1,
                                        unsigned& r2, unsigned& r3, unsigned a) {
    asm volatile("ldmatrix.sync.aligned.m8n8.x4.shared.b16 {%0,%1,%2,%3},[%4];\n"
                 : "=r"(r0), "=r"(r1), "=r"(r2), "=r"(r3) : "r"(a));
}
__device__ __forceinline__ void ldsm_x4_t(unsigned& r0, unsigned& r1,
                                          unsigned& r2, unsigned& r3, unsigned a) {
    asm volatile("ldmatrix.sync.aligned.m8n8.x4.trans.shared.b16 {%0,%1,%2,%3},[%4];\n"
                 : "=r"(r0), "=r"(r1), "=r"(r2), "=r"(r3) : "r"(a));
}
__device__ __forceinline__ void mma16816(float* d, unsigned a0, unsigned a1,
                                         unsigned a2, unsigned a3,
                                         unsigned b0, unsigned b1) {
    asm volatile("mma.sync.aligned.m16n8k16.row.col.f32.f16.f16.f32 "
                 "{%0,%1,%2,%3},{%4,%5,%6,%7},{%8,%9},{%0,%1,%2,%3};\n"
                 : "+f"(d[0]), "+f"(d[1]), "+f"(d[2]), "+f"(d[3])
                 : "r"(a0), "r"(a1), "r"(a2), "r"(a3), "r"(b0), "r"(b1));
}

// ---------------------------- CSR construction -----------------------------
__global__ void hist_kernel(const int4* __restrict__ dst4) {
    int i = blockIdx.x * blockDim.x + threadIdx.x;
    if (i < N_EDGES / 4) {
        int4 d = dst4[i];
        atomicAdd(&g_deg[d.x], 1);
        atomicAdd(&g_deg[d.y], 1);
        atomicAdd(&g_deg[d.z], 1);
        atomicAdd(&g_deg[d.w], 1);
    }
}

// one block, whole scan in smem (~200KB dynamic)
__global__ void scan_fused_kernel() {
    extern __shared__ int sdeg[];
    __shared__ int warpsum[32];
    int t = threadIdx.x;
    for (int i = t; i < SCAN_PAD; i += SCAN_T)
        sdeg[i] = (i < N_NODES) ? g_deg[i] : 0;
    __syncthreads();

    int base = t * CHUNK;
    int sum = 0;
    for (int j = 0; j < CHUNK; j++) sum += sdeg[base + j];

    int lane = t & 31, wid = t >> 5;
    int incl = sum;
#pragma unroll
    for (int o = 1; o < 32; o <<= 1) {
        int u = __shfl_up_sync(0xffffffffu, incl, o);
        if (lane >= o) incl += u;
    }
    if (lane == 31) warpsum[wid] = incl;
    __syncthreads();
    if (wid == 0) {
        int v = warpsum[lane];
        int wi = v;
#pragma unroll
        for (int o = 1; o < 32; o <<= 1) {
            int u = __shfl_up_sync(0xffffffffu, wi, o);
            if (lane >= o) wi += u;
        }
        warpsum[lane] = wi - v;
        if (lane == 31) g_rowptr[N_NODES] = wi;
    }
    __syncthreads();

    int run = warpsum[wid] + (incl - sum);
    for (int j = 0; j < CHUNK; j++) {
        int d = sdeg[base + j];
        sdeg[base + j] = run;
        run += d;
    }
    __syncthreads();
    for (int i = t; i < N_NODES; i += SCAN_T) {
        int v = sdeg[i];
        g_rowptr[i] = v;
        g_cursor[i] = v;
    }
}

__global__ void scatter_kernel(const int4* __restrict__ src4,
                               const int4* __restrict__ dst4,
                               const float4* __restrict__ w4) {
    int i = blockIdx.x * blockDim.x + threadIdx.x;
    if (i >= N_EDGES / 4) return;
    int4   s = src4[i];
    int4   d = dst4[i];
    float4 w = w4[i];
    int p0 = atomicAdd(&g_cursor[d.x], 1);
    int p1 = atomicAdd(&g_cursor[d.y], 1);
    int p2 = atomicAdd(&g_cursor[d.z], 1);
    int p3 = atomicAdd(&g_cursor[d.w], 1);
    g_edge[p0] = make_int2(s.x, __float_as_int(w.x));
    g_edge[p1] = make_int2(s.y, __float_as_int(w.y));
    g_edge[p2] = make_int2(s.z, __float_as_int(w.z));
    g_edge[p3] = make_int2(s.w, __float_as_int(w.w));
}

// ------------------- HMMA GEMM: 64 rows x 64 cols per block -----------------
// 4 warps; warp w computes n-strip [16w,16w+16). A fp32->fp16 staged row-major,
// W fp32->fp16 staged [k][n]; ldmatrix + mma.sync m16n8k16, fp32 accum, half out.
__global__ void gemm64_hmma_kernel(const float* __restrict__ A,
                                   const float* __restrict__ W,
                                   __half* __restrict__ outh) {
    __shared__ __align__(16) __half As[64 * 72];
    __shared__ __align__(16) __half Ws[64 * 72];
    const int tid  = threadIdx.x;
    const int lane = tid & 31;
    const int w    = tid >> 5;
    const int row0 = blockIdx.x * 64;

    // stage W [k][n] (64x64): 1024 float4 across 128 threads
    const float4* W4 = reinterpret_cast<const float4*>(W);
    for (int i = tid; i < 1024; i += 128) {
        float4 v = W4[i];
        int k = i >> 4, n = (i & 15) * 4;
        __half2* p = reinterpret_cast<__half2*>(&Ws[k * 72 + n]);
        p[0] = __floats2half2_rn(v.x, v.y);
        p[1] = __floats2half2_rn(v.z, v.w);
    }
    // stage A rows (64x64)
    const float4* A4 = reinterpret_cast<const float4*>(A);
    for (int i = tid; i < 1024; i += 128) {
        int r = i >> 4, k = (i & 15) * 4;
        int grow = row0 + r;
        float4 v = (grow < N_NODES) ? A4[grow * 16 + (k >> 2)]
                                    : make_float4(0.f, 0.f, 0.f, 0.f);
        __half2* p = reinterpret_cast<__half2*>(&As[r * 72 + k]);
        p[0] = __floats2half2_rn(v.x, v.y);
        p[1] = __floats2half2_rn(v.z, v.w);
    }
    __syncthreads();

    float d[4][2][4];
#pragma unroll
    for (int m = 0; m < 4; m++)
#pragma unroll
        for (int j = 0; j < 2; j++)
#pragma unroll
            for (int c = 0; c < 4; c++) d[m][j][c] = 0.f;

    const int lrow = lane & 15;        // ldmatrix row within 16
    const int lcol = (lane >> 4) * 8;  // ldmatrix col-block

#pragma unroll
    for (int ks = 0; ks < 4; ks++) {
        const int kk = ks * 16;
        unsigned b0, b1, b2, b3;
        ldsm_x4_t(b0, b1, b2, b3,
                  smem_u32(&Ws[(kk + lrow) * 72 + w * 16 + lcol]));
#pragma unroll
        for (int m = 0; m < 4; m++) {
            unsigned a0, a1, a2, a3;
            ldsm_x4(a0, a1, a2, a3,
                    smem_u32(&As[(m * 16 + lrow) * 72 + kk + lcol]));
            mma16816(d[m][0], a0, a1, a2, a3, b0, b1);
            mma16816(d[m][1], a0, a1, a2, a3, b2, b3);
        }
    }

    // write: d[m][j]: rows m*16+(lane>>2)+{0,8}, cols w*16+j*8+(lane&3)*2+{0,1}
    __half2* out2 = reinterpret_cast<__half2*>(outh);
    const int r_in = lane >> 2;
    const int cpair = (lane & 3);
#pragma unroll
    for (int m = 0; m < 4; m++) {
#pragma unroll
        for (int j = 0; j < 2; j++) {
            int col2 = (w * 16 + j * 8) / 2 + cpair;   // half2 index
            int g0 = row0 + m * 16 + r_in;
            int g1 = g0 + 8;
            if (g0 < N_NODES)
                out2[g0 * 32 + col2] = __floats2half2_rn(d[m][j][0], d[m][j][1]);
            if (g1 < N_NODES)
                out2[g1 * 32 + col2] = __floats2half2_rn(d[m][j][2], d[m][j][3]);
        }
    }
}

// -------------------- CSR aggregation + bias + swish ------------------------
__global__ void agg_swish_kernel(const __half2* __restrict__ hp,
                                 const float* __restrict__ bias,
                                 float* __restrict__ out) {
    int warp = (blockIdx.x * blockDim.x + threadIdx.x) >> 5;
    int lane = threadIdx.x & 31;
    if (warp >= N_NODES) return;
    int beg = g_rowptr[warp];
    int end = g_rowptr[warp + 1];
    float2 acc = make_float2(0.f, 0.f);
    int e = beg;
    for (; e + 8 <= end; e += 8) {
        int2 ed[8];
#pragma unroll
        for (int j = 0; j < 8; j++) ed[j] = g_edge[e + j];
        float2 v[8];
#pragma unroll
        for (int j = 0; j < 8; j++) v[j] = __half22float2(hp[ed[j].x * 32 + lane]);
#pragma unroll
        for (int j = 0; j < 8; j++) {
            float w = __int_as_float(ed[j].y);
            acc.x = fmaf(w, v[j].x, acc.x);
            acc.y = fmaf(w, v[j].y, acc.y);
        }
    }
    for (; e + 2 <= end; e += 2) {
        int2 e0 = g_edge[e], e1 = g_edge[e + 1];
        float2 v0 = __half22float2(hp[e0.x * 32 + lane]);
        float2 v1 = __half22float2(hp[e1.x * 32 + lane]);
        float w0 = __int_as_float(e0.y), w1 = __int_as_float(e1.y);
        acc.x = fmaf(w0, v0.x, acc.x); acc.y = fmaf(w0, v0.y, acc.y);
        acc.x = fmaf(w1, v1.x, acc.x); acc.y = fmaf(w1, v1.y, acc.y);
    }
    if (e < end) {
        int2 e0 = g_edge[e];
        float2 v0 = __half22float2(hp[e0.x * 32 + lane]);
        float w0 = __int_as_float(e0.y);
        acc.x = fmaf(w0, v0.x, acc.x); acc.y = fmaf(w0, v0.y, acc.y);
    }
    float2 b = reinterpret_cast<const float2*>(bias)[lane];
    float ax = acc.x + b.x;
    float ay = acc.y + b.y;
    ax = ax / (1.f + __expf(-ax));
    ay = ay / (1.f + __expf(-ay));
    reinterpret_cast<float2*>(out)[warp * 32 + lane] = make_float2(ax, ay);
}

// --------------- fused dense(100, swish) + dense(1, sigmoid) ----------------
__global__ void gemm100_head_kernel(const float* __restrict__ A,
                                    const float* __restrict__ Wd,
                                    const float* __restrict__ bd,
                                    const float* __restrict__ Wo,
                                    const float* __restrict__ bo,
                                    float* __restrict__ out) {
    extern __shared__ float sm[];
    float* Ast  = sm;                       // [64][132]
    float* Ws   = Ast + 64 * 132;           // [64][104]
    float* part = Ws + 64 * 104;            // [128][26]
    float* woS  = part + 128 * 26;          // [100]
    const int tx = threadIdx.x;             // 0..24
    const int ty = threadIdx.y;             // 0..15
    const int tid = ty * 25 + tx;           // 0..399
    const int row0 = blockIdx.x * 128;

    for (int i = tid * 4; i < 6400; i += 1600) {
        int k = i / 100, c = i % 100;
        float4 v = *reinterpret_cast<const float4*>(Wd + i);
        *reinterpret_cast<float4*>(&Ws[k * 104 + c]) = v;
    }
    for (int i = tid * 4; i < 8192; i += 1600) {
        int r = i >> 6, k = i & 63;
        int grow = row0 + r;
        float4 v = (grow < N_NODES)
                 ? *reinterpret_cast<const float4*>(A + grow * 64 + k)
                 : make_float4(0.f, 0.f, 0.f, 0.f);
        Ast[(k + 0) * 132 + r] = v.x;
        Ast[(k + 1) * 132 + r] = v.y;
        Ast[(k + 2) * 132 + r] = v.z;
        Ast[(k + 3) * 132 + r] = v.w;
    }
    if (tid < 100) woS[tid] = Wo[tid];
    __syncthreads();

    float acc[8][4];
#pragma unroll
    for (int r = 0; r < 8; r++)
#pragma unroll
        for (int c = 0; c < 4; c++) acc[r][c] = 0.f;

#pragma unroll 2
    for (int k = 0; k < 64; k++) {
        float4 wv = *reinterpret_cast<const float4*>(&Ws[k * 104 + tx * 4]);
        float4 a0 = *reinterpret_cast<const float4*>(&Ast[k * 132 + ty * 8]);
        float4 a1 = *reinterpret_cast<const float4*>(&Ast[k * 132 + ty * 8 + 4]);
        float av[8] = {a0.x, a0.y, a0.z, a0.w, a1.x, a1.y, a1.z, a1.w};
#pragma unroll
        for (int r = 0; r < 8; r++) {
            acc[r][0] = fmaf(av[r], wv.x, acc[r][0]);
            acc[r][1] = fmaf(av[r], wv.y, acc[r][1]);
            acc[r][2] = fmaf(av[r], wv.z, acc[r][2]);
            acc[r][3] = fmaf(av[r], wv.w, acc[r][3]);
        }
    }

    float4 bv  = *reinterpret_cast<const float4*>(bd + tx * 4);
    float4 wo4 = *reinterpret_cast<const float4*>(&woS[tx * 4]);
#pragma unroll
    for (int r = 0; r < 8; r++) {
        float v0 = acc[r][0] + bv.x;
        float v1 = acc[r][1] + bv.y;
        float v2 = acc[r][2] + bv.z;
        float v3 = acc[r][3] + bv.w;
        v0 = v0 / (1.f + __expf(-v0));
        v1 = v1 / (1.f + __expf(-v1));
        v2 = v2 / (1.f + __expf(-v2));
        v3 = v3 / (1.f + __expf(-v3));
        part[(ty * 8 + r) * 26 + tx] = v0 * wo4.x + v1 * wo4.y + v2 * wo4.z + v3 * wo4.w;
    }
    __syncthreads();

    if (tid < 128) {
        int grow = row0 + tid;
        if (grow < N_NODES) {
            float s = 0.f;
#pragma unroll
            for (int j = 0; j < 25; j++) s += part[tid * 26 + j];
            out[grow] = 1.f / (1.f + __expf(-(s + bo[0])));
        }
    }
}

// -------------------------------- launcher ----------------------------------
extern "C" void kernel_launch(void* const* d_in, const int* in_sizes, int n_in,
                              void* d_out, int out_size) {
    const float* x    = (const float*)d_in[0];
    const int*   esrc = (const int*)  d_in[1];
    const int*   edst = (const int*)  d_in[2];
    const float* ew   = (const float*)d_in[3];
    const float* W1   = (const float*)d_in[4];
    const float* b1   = (const float*)d_in[5];
    const float* W2   = (const float*)d_in[6];
    const float* b2   = (const float*)d_in[7];
    const float* Wd   = (const float*)d_in[8];
    const float* bd   = (const float*)d_in[9];
    const float* Wo   = (const float*)d_in[10];
    const float* bo   = (const float*)d_in[11];
    float* out = (float*)d_out;

    __half* h1h;  float* h2;  int* degp;
    cudaGetSymbolAddress((void**)&h1h,  g_h1h);
    cudaGetSymbolAddress((void**)&h2,   g_h2);
    cudaGetSymbolAddress((void**)&degp, g_deg);

    cudaFuncSetAttribute(scan_fused_kernel,
                         cudaFuncAttributeMaxDynamicSharedMemorySize,
                         SCAN_PAD * (int)sizeof(int));
    cudaFuncSetAttribute(gemm100_head_kernel,
                         cudaFuncAttributeMaxDynamicSharedMemorySize, HEAD_SMEM);

    // --- CSR build ---
    cudaMemsetAsync(degp, 0, N_NODES * sizeof(int));
    hist_kernel<<<(N_EDGES / 4 + 255) / 256, 256>>>((const int4*)edst);
    scan_fused_kernel<<<1, SCAN_T, SCAN_PAD * sizeof(int)>>>();
    scatter_kernel<<<(N_EDGES / 4 + 255) / 256, 256>>>((const int4*)esrc,
                                                       (const int4*)edst,
                                                       (const float4*)ew);

    const int aggBlocks   = (N_NODES * 32 + 255) / 256;
    const int gemmBlocks  = (N_NODES + 63) / 64;
    const int headBlocks  = (N_NODES + 127) / 128;

    // --- layer 1 ---
    gemm64_hmma_kernel<<<gemmBlocks, 128>>>(x, W1, h1h);
    agg_swish_kernel<<<aggBlocks, 256>>>((const __half2*)h1h, b1, h2);

    // --- layer 2 ---
    gemm64_hmma_kernel<<<gemmBlocks, 128>>>(h2, W2, h1h);
    agg_swish_kernel<<<aggBlocks, 256>>>((const __half2*)h1h, b2, h2);

    // --- dense head (fused) ---
    gemm100_head_kernel<<<headBlocks, dim3(25, 16), HEAD_SMEM>>>(h2, Wd, bd, Wo, bo, out);
}